// round 2
// baseline (speedup 1.0000x reference)
#include <cuda_runtime.h>

#define N_NODES 100000
#define N_EDGES 20000
#define N_INC   800000
#define TD      384
#define HID     128
#define NPART   1024

// ---------------- device scratch (static, no runtime allocation) ----------------
__device__ __align__(16) float g_hA[N_NODES * HID];
__device__ __align__(16) float g_hB[N_NODES * HID];
__device__ __align__(16) float g_ef[N_EDGES * HID];
__device__ int   g_ecnt[N_EDGES];
__device__ int   g_ncnt[N_NODES];
__device__ int   g_ecur[N_EDGES];
__device__ int   g_ncur[N_NODES];
__device__ int   g_eoff[N_EDGES + 1];
__device__ int   g_noff[N_NODES + 1];
__device__ int   g_enodes[N_INC];   // CSR by edge: node ids
__device__ int   g_nedges[N_INC];   // CSR by node: edge ids
__device__ int   g_bsum[512];
__device__ float g_part[NPART * HID];
__device__ __align__(16) float g_scale[HID];

// ---------------- f32x2 helpers (FFMA2 is PTX-only) ----------------
__device__ __forceinline__ unsigned long long pk2(float x, float y) {
    unsigned long long r;
    asm("mov.b64 %0, {%1, %2};" : "=l"(r) : "f"(x), "f"(y));
    return r;
}
__device__ __forceinline__ void fma2(unsigned long long& acc, unsigned long long a,
                                     unsigned long long b) {
    asm("fma.rn.f32x2 %0, %1, %2, %0;" : "+l"(acc) : "l"(a), "l"(b));
}
__device__ __forceinline__ float2 upk(unsigned long long v) {
    float2 r;
    asm("mov.b64 {%0, %1}, %2;" : "=f"(r.x), "=f"(r.y) : "l"(v));
    return r;
}

// ---------------- CSR construction ----------------
__global__ void zero_counts() {
    int i = blockIdx.x * blockDim.x + threadIdx.x;
    if (i < N_EDGES) { g_ecnt[i] = 0; g_ecur[i] = 0; }
    if (i < N_NODES) { g_ncnt[i] = 0; g_ncur[i] = 0; }
}

__global__ void hist_kernel(const int* __restrict__ ni, const int* __restrict__ ei) {
    int i = blockIdx.x * blockDim.x + threadIdx.x;
    if (i < N_INC) {
        atomicAdd(&g_ecnt[ei[i]], 1);
        atomicAdd(&g_ncnt[ni[i]], 1);
    }
}

// sel: 0 = edge counts, 1 = node counts
__global__ void seg_block_sums(int sel) {
    const int* __restrict__ cnt = sel ? g_ncnt : g_ecnt;
    int n = sel ? N_NODES : N_EDGES;
    __shared__ int s[256];
    int t = threadIdx.x;
    int i = blockIdx.x * 256 + t;
    s[t] = (i < n) ? cnt[i] : 0;
    __syncthreads();
    for (int o = 128; o > 0; o >>= 1) {
        if (t < o) s[t] += s[t + o];
        __syncthreads();
    }
    if (t == 0) g_bsum[blockIdx.x] = s[0];
}

__global__ void scan_bsums(int nb) {
    __shared__ int s[512];
    int t = threadIdx.x;
    int v = (t < nb) ? g_bsum[t] : 0;
    s[t] = v;
    __syncthreads();
    for (int o = 1; o < 512; o <<= 1) {
        int x = (t >= o) ? s[t - o] : 0;
        __syncthreads();
        s[t] += x;
        __syncthreads();
    }
    if (t < nb) g_bsum[t] = s[t] - v;  // exclusive
}

// sel: 0 = edge offsets, 1 = node offsets
__global__ void scan_final(int sel) {
    const int* __restrict__ cnt = sel ? g_ncnt : g_ecnt;
    int* __restrict__ off = sel ? g_noff : g_eoff;
    int n = sel ? N_NODES : N_EDGES;
    __shared__ int s[256];
    int t = threadIdx.x;
    int i = blockIdx.x * 256 + t;
    int v = (i < n) ? cnt[i] : 0;
    s[t] = v;
    __syncthreads();
    for (int o = 1; o < 256; o <<= 1) {
        int x = (t >= o) ? s[t - o] : 0;
        __syncthreads();
        s[t] += x;
        __syncthreads();
    }
    if (i < n) off[i] = g_bsum[blockIdx.x] + s[t] - v;
    if (i == 0) off[n] = N_INC;
}

__global__ void csr_fill(const int* __restrict__ ni, const int* __restrict__ ei) {
    int i = blockIdx.x * blockDim.x + threadIdx.x;
    if (i >= N_INC) return;
    int e = ei[i], n = ni[i];
    int pe = g_eoff[e] + atomicAdd(&g_ecur[e], 1);
    g_enodes[pe] = n;
    int pn = g_noff[n] + atomicAdd(&g_ncur[n], 1);
    g_nedges[pn] = e;
}

// ---------------- projection GEMM: g_hA[M,128] = A[M,384] @ B[384,128] + bias ----------------
// 128x128 block tile, BK=8, 256 threads, 8x8 microtile (split halves),
// f32x2 packed FMA accumulators. Writes g_hA directly (device global).
__global__ void __launch_bounds__(256) gemm_proj(
    const float* __restrict__ A, const float* __restrict__ B,
    const float* __restrict__ bias) {
    __shared__ __align__(16) float As[8][128];
    __shared__ __align__(16) float Bs[8][128];
    const int tid = threadIdx.x;
    const int bm = blockIdx.x * 128;
    const int a_r = tid >> 1;
    const int a_c = (tid & 1) * 4;
    const int b_r = tid >> 5;
    const int b_c = (tid & 31) * 4;
    const int tx = tid & 15;
    const int ty = tid >> 4;

    int arow = bm + a_r;
    if (arow >= N_NODES) arow = N_NODES - 1;  // clamp loads, mask stores
    const float* Aptr = A + (size_t)arow * TD + a_c;

    unsigned long long acc[8][4];
#pragma unroll
    for (int i = 0; i < 8; i++)
#pragma unroll
        for (int j = 0; j < 4; j++) acc[i][j] = 0ULL;

    for (int k0 = 0; k0 < TD; k0 += 8) {
        float4 av = *(const float4*)(Aptr + k0);
        float4 bv = *(const float4*)(B + (k0 + b_r) * HID + b_c);
        As[a_c + 0][a_r] = av.x;
        As[a_c + 1][a_r] = av.y;
        As[a_c + 2][a_r] = av.z;
        As[a_c + 3][a_r] = av.w;
        *(float4*)&Bs[b_r][b_c] = bv;
        __syncthreads();
#pragma unroll
        for (int k = 0; k < 8; k++) {
            float4 a0 = *(const float4*)&As[k][ty * 4];
            float4 a1 = *(const float4*)&As[k][64 + ty * 4];
            ulonglong2 bb0 = *(const ulonglong2*)&Bs[k][tx * 4];
            ulonglong2 bb1 = *(const ulonglong2*)&Bs[k][64 + tx * 4];
            unsigned long long bp0 = bb0.x, bp1 = bb0.y, bp2 = bb1.x, bp3 = bb1.y;
            float aval[8] = {a0.x, a0.y, a0.z, a0.w, a1.x, a1.y, a1.z, a1.w};
#pragma unroll
            for (int i = 0; i < 8; i++) {
                unsigned long long ad = pk2(aval[i], aval[i]);
                fma2(acc[i][0], ad, bp0);
                fma2(acc[i][1], ad, bp1);
                fma2(acc[i][2], ad, bp2);
                fma2(acc[i][3], ad, bp3);
            }
        }
        __syncthreads();
    }

    float4 blo = *(const float4*)(bias + tx * 4);
    float4 bhi = *(const float4*)(bias + 64 + tx * 4);
#pragma unroll
    for (int i = 0; i < 8; i++) {
        int row = bm + ((i < 4) ? (ty * 4 + i) : (64 + ty * 4 + i - 4));
        if (row < N_NODES) {
            float2 p0 = upk(acc[i][0]), p1 = upk(acc[i][1]);
            float2 p2 = upk(acc[i][2]), p3 = upk(acc[i][3]);
            float4 o0 = {p0.x + blo.x, p0.y + blo.y, p1.x + blo.z, p1.y + blo.w};
            float4 o1 = {p2.x + bhi.x, p2.y + bhi.y, p3.x + bhi.z, p3.y + bhi.w};
            *(float4*)(g_hA + (size_t)row * HID + tx * 4) = o0;
            *(float4*)(g_hA + (size_t)row * HID + 64 + tx * 4) = o1;
        }
    }
}

// ---------------- column mean (partials) + hypernetwork scale ----------------
// sel: 0 = read g_hA, 1 = read g_hB
__global__ void col_partial(int sel) {
    const float* __restrict__ h = sel ? g_hB : g_hA;
    float s = 0.f;
    int c = threadIdx.x;
    for (int r = blockIdx.x; r < N_NODES; r += gridDim.x)
        s += h[(size_t)r * HID + c];
    g_part[blockIdx.x * HID + c] = s;
}

__global__ void mk_scale(const float* __restrict__ W1, const float* __restrict__ b1,
                         const float* __restrict__ W2, const float* __restrict__ b2) {
    __shared__ float g[HID];
    __shared__ float t1[HID];
    int j = threadIdx.x;
    float s = 0.f;
    for (int b = 0; b < NPART; b++) s += g_part[b * HID + j];
    g[j] = s * (1.0f / (float)N_NODES);
    __syncthreads();
    float a = b1[j];
    for (int k = 0; k < HID; k++) a += g[k] * W1[k * HID + j];
    t1[j] = fmaxf(a, 0.f);
    __syncthreads();
    float o = b2[j];
    for (int k = 0; k < HID; k++) o += t1[k] * W2[k * HID + j];
    g_scale[j] = o;
}

// ---------------- aggregation: warp-per-segment, atomic-free, MLP=4 ----------------
// sel: 0 = read g_hA, 1 = read g_hB. Writes g_ef.
__global__ void edge_agg(int sel) {
    const float4* __restrict__ h4 = (const float4*)(sel ? g_hB : g_hA);
    int w = (blockIdx.x * blockDim.x + threadIdx.x) >> 5;
    int lane = threadIdx.x & 31;
    if (w >= N_EDGES) return;
    int beg = g_eoff[w], end = g_eoff[w + 1];
    float4 acc = make_float4(0.f, 0.f, 0.f, 0.f);
    for (int c = beg; c < end; c += 32) {
        int m = end - c;
        if (m > 32) m = 32;
        int myid = (lane < m) ? g_enodes[c + lane] : 0;
        int t = 0;
        for (; t + 4 <= m; t += 4) {
            int n0 = __shfl_sync(0xffffffffu, myid, t + 0);
            int n1 = __shfl_sync(0xffffffffu, myid, t + 1);
            int n2 = __shfl_sync(0xffffffffu, myid, t + 2);
            int n3 = __shfl_sync(0xffffffffu, myid, t + 3);
            float4 v0 = h4[(size_t)n0 * 32 + lane];
            float4 v1 = h4[(size_t)n1 * 32 + lane];
            float4 v2 = h4[(size_t)n2 * 32 + lane];
            float4 v3 = h4[(size_t)n3 * 32 + lane];
            acc.x += v0.x + v1.x + v2.x + v3.x;
            acc.y += v0.y + v1.y + v2.y + v3.y;
            acc.z += v0.z + v1.z + v2.z + v3.z;
            acc.w += v0.w + v1.w + v2.w + v3.w;
        }
        for (; t < m; t++) {
            int nid = __shfl_sync(0xffffffffu, myid, t);
            float4 v = h4[(size_t)nid * 32 + lane];
            acc.x += v.x; acc.y += v.y; acc.z += v.z; acc.w += v.w;
        }
    }
    float inv = 1.0f / fmaxf((float)(end - beg), 1.0f);
    float4 o = make_float4(acc.x * inv, acc.y * inv, acc.z * inv, acc.w * inv);
    ((float4*)g_ef)[(size_t)w * 32 + lane] = o;
}

// to_out: 0 = write g_hB, 1 = write provided out pointer (d_out)
__global__ void node_agg(float4* __restrict__ out_arg, int to_out) {
    float4* __restrict__ out = to_out ? out_arg : (float4*)g_hB;
    int w = (blockIdx.x * blockDim.x + threadIdx.x) >> 5;
    int lane = threadIdx.x & 31;
    if (w >= N_NODES) return;
    int beg = g_noff[w], end = g_noff[w + 1];
    const float4* ef4 = (const float4*)g_ef;
    float4 acc = make_float4(0.f, 0.f, 0.f, 0.f);
    for (int c = beg; c < end; c += 32) {
        int m = end - c;
        if (m > 32) m = 32;
        int myid = (lane < m) ? g_nedges[c + lane] : 0;
        int t = 0;
        for (; t + 4 <= m; t += 4) {
            int e0 = __shfl_sync(0xffffffffu, myid, t + 0);
            int e1 = __shfl_sync(0xffffffffu, myid, t + 1);
            int e2 = __shfl_sync(0xffffffffu, myid, t + 2);
            int e3 = __shfl_sync(0xffffffffu, myid, t + 3);
            float4 v0 = ef4[(size_t)e0 * 32 + lane];
            float4 v1 = ef4[(size_t)e1 * 32 + lane];
            float4 v2 = ef4[(size_t)e2 * 32 + lane];
            float4 v3 = ef4[(size_t)e3 * 32 + lane];
            acc.x += v0.x + v1.x + v2.x + v3.x;
            acc.y += v0.y + v1.y + v2.y + v3.y;
            acc.z += v0.z + v1.z + v2.z + v3.z;
            acc.w += v0.w + v1.w + v2.w + v3.w;
        }
        for (; t < m; t++) {
            int eid = __shfl_sync(0xffffffffu, myid, t);
            float4 v = ef4[(size_t)eid * 32 + lane];
            acc.x += v.x; acc.y += v.y; acc.z += v.z; acc.w += v.w;
        }
    }
    float inv = 1.0f / fmaxf((float)(end - beg), 1.0f);
    float4 sc = ((const float4*)g_scale)[lane];
    float4 o;
    o.x = fmaxf(acc.x * inv * sc.x, 0.f);
    o.y = fmaxf(acc.y * inv * sc.y, 0.f);
    o.z = fmaxf(acc.z * inv * sc.z, 0.f);
    o.w = fmaxf(acc.w * inv * sc.w, 0.f);
    out[(size_t)w * 32 + lane] = o;
}

// ---------------- launch ----------------
extern "C" void kernel_launch(void* const* d_in, const int* in_sizes, int n_in,
                              void* d_out, int out_size) {
    const float* text = (const float*)d_in[0];
    const float* Wp   = (const float*)d_in[1];
    const float* bp   = (const float*)d_in[2];
    const float* W1a  = (const float*)d_in[3];
    const float* b1a  = (const float*)d_in[4];
    const float* W2a  = (const float*)d_in[5];
    const float* b2a  = (const float*)d_in[6];
    const float* W1b  = (const float*)d_in[7];
    const float* b1b  = (const float*)d_in[8];
    const float* W2b  = (const float*)d_in[9];
    const float* b2b  = (const float*)d_in[10];
    const int* node_idx = (const int*)d_in[11];
    const int* edge_idx = (const int*)d_in[12];

    const int NBE = (N_EDGES + 255) / 256;   // 79
    const int NBN = (N_NODES + 255) / 256;   // 391
    const int NBI = (N_INC + 255) / 256;     // 3125

    // CSR build
    zero_counts<<<NBN, 256>>>();
    hist_kernel<<<NBI, 256>>>(node_idx, edge_idx);
    seg_block_sums<<<NBE, 256>>>(0);
    scan_bsums<<<1, 512>>>(NBE);
    scan_final<<<NBE, 256>>>(0);
    seg_block_sums<<<NBN, 256>>>(1);
    scan_bsums<<<1, 512>>>(NBN);
    scan_final<<<NBN, 256>>>(1);
    csr_fill<<<NBI, 256>>>(node_idx, edge_idx);

    // projection -> g_hA
    gemm_proj<<<(N_NODES + 127) / 128, 256>>>(text, Wp, bp);

    // layer 1: read g_hA, write g_hB
    col_partial<<<NPART, 128>>>(0);
    mk_scale<<<1, 128>>>(W1a, b1a, W2a, b2a);
    edge_agg<<<N_EDGES / 8, 256>>>(0);
    node_agg<<<N_NODES / 8, 256>>>((float4*)d_out, 0);

    // layer 2: read g_hB, write d_out
    col_partial<<<NPART, 128>>>(1);
    mk_scale<<<1, 128>>>(W1b, b1b, W2b, b2b);
    edge_agg<<<N_EDGES / 8, 256>>>(1);
    node_agg<<<N_NODES / 8, 256>>>((float4*)d_out, 1);
}

// round 3
// speedup vs baseline: 1.6008x; 1.6008x over previous
#include <cuda_runtime.h>
#include <cuda_fp16.h>
#include <cuda_bf16.h>

#define N_NODES 100000
#define N_EDGES 20000
#define N_INC   800000
#define TD      384
#define HID     128
#define NPART   1024

// ---------------- device scratch ----------------
__device__ __align__(16) __half g_h16A[N_NODES * HID];
__device__ __align__(16) __half g_h16B[N_NODES * HID];
__device__ __align__(16) __half g_ef16[N_EDGES * HID];
__device__ __nv_bfloat16 g_WtH[HID * TD];   // W transposed [n][k], hi part
__device__ __nv_bfloat16 g_WtL[HID * TD];   // lo part
__device__ int   g_ecnt[N_EDGES];
__device__ int   g_ncnt[N_NODES];
__device__ int   g_ecur[N_EDGES];
__device__ int   g_ncur[N_NODES];
__device__ int   g_eoff[N_EDGES + 1];
__device__ int   g_noff[N_NODES + 1];
__device__ int   g_enodes[N_INC];
__device__ int   g_nedges[N_INC];
__device__ int   g_bsum[512];
__device__ float g_part[NPART * HID];
__device__ __align__(16) float g_scale[HID];

// ---------------- fp16 vec helpers ----------------
__device__ __forceinline__ float4 load4h(const __half* row, int lane) {
    uint2 v = ((const uint2*)row)[lane];
    __half2 a = *reinterpret_cast<__half2*>(&v.x);
    __half2 b = *reinterpret_cast<__half2*>(&v.y);
    float2 fa = __half22float2(a), fb = __half22float2(b);
    return make_float4(fa.x, fa.y, fb.x, fb.y);
}
__device__ __forceinline__ void store4h(__half* row, int lane, float4 v) {
    __half2 a = __floats2half2_rn(v.x, v.y);
    __half2 b = __floats2half2_rn(v.z, v.w);
    uint2 u;
    u.x = *reinterpret_cast<unsigned*>(&a);
    u.y = *reinterpret_cast<unsigned*>(&b);
    ((uint2*)row)[lane] = u;
}

// ---------------- CSR construction ----------------
__global__ void zero_counts() {
    int i = blockIdx.x * blockDim.x + threadIdx.x;
    if (i < N_EDGES) { g_ecnt[i] = 0; g_ecur[i] = 0; }
    if (i < N_NODES) { g_ncnt[i] = 0; g_ncur[i] = 0; }
}

__global__ void hist_kernel(const int* __restrict__ ni, const int* __restrict__ ei) {
    int i = blockIdx.x * blockDim.x + threadIdx.x;
    if (i < N_INC) {
        atomicAdd(&g_ecnt[ei[i]], 1);
        atomicAdd(&g_ncnt[ni[i]], 1);
    }
}

__global__ void seg_block_sums(int sel) {
    const int* __restrict__ cnt = sel ? g_ncnt : g_ecnt;
    int n = sel ? N_NODES : N_EDGES;
    __shared__ int s[256];
    int t = threadIdx.x;
    int i = blockIdx.x * 256 + t;
    s[t] = (i < n) ? cnt[i] : 0;
    __syncthreads();
    for (int o = 128; o > 0; o >>= 1) {
        if (t < o) s[t] += s[t + o];
        __syncthreads();
    }
    if (t == 0) g_bsum[blockIdx.x] = s[0];
}

__global__ void scan_bsums(int nb) {
    __shared__ int s[512];
    int t = threadIdx.x;
    int v = (t < nb) ? g_bsum[t] : 0;
    s[t] = v;
    __syncthreads();
    for (int o = 1; o < 512; o <<= 1) {
        int x = (t >= o) ? s[t - o] : 0;
        __syncthreads();
        s[t] += x;
        __syncthreads();
    }
    if (t < nb) g_bsum[t] = s[t] - v;
}

__global__ void scan_final(int sel) {
    const int* __restrict__ cnt = sel ? g_ncnt : g_ecnt;
    int* __restrict__ off = sel ? g_noff : g_eoff;
    int n = sel ? N_NODES : N_EDGES;
    __shared__ int s[256];
    int t = threadIdx.x;
    int i = blockIdx.x * 256 + t;
    int v = (i < n) ? cnt[i] : 0;
    s[t] = v;
    __syncthreads();
    for (int o = 1; o < 256; o <<= 1) {
        int x = (t >= o) ? s[t - o] : 0;
        __syncthreads();
        s[t] += x;
        __syncthreads();
    }
    if (i < n) off[i] = g_bsum[blockIdx.x] + s[t] - v;
    if (i == 0) off[n] = N_INC;
}

__global__ void csr_fill(const int* __restrict__ ni, const int* __restrict__ ei) {
    int i = blockIdx.x * blockDim.x + threadIdx.x;
    if (i >= N_INC) return;
    int e = ei[i], n = ni[i];
    int pe = g_eoff[e] + atomicAdd(&g_ecur[e], 1);
    g_enodes[pe] = n;
    int pn = g_noff[n] + atomicAdd(&g_ncur[n], 1);
    g_nedges[pn] = e;
}

// ---------------- W prep: fp32 [k][n] -> bf16 hi/lo transposed [n][k] ----------------
__global__ void w_prep(const float* __restrict__ W) {
    int i = blockIdx.x * blockDim.x + threadIdx.x;
    if (i >= TD * HID) return;
    int n = i & (HID - 1);
    int k = i >> 7;
    float x = W[k * HID + n];
    __nv_bfloat16 hi = __float2bfloat16(x);
    float lo = x - __bfloat162float(hi);
    g_WtH[n * TD + k] = hi;
    g_WtL[n * TD + k] = __float2bfloat16(lo);
}

// ---------------- tensor-core projection GEMM (bf16-split, mma.sync) ----------------
// h16A[M,128] = A[M,384] @ W[384,128] + bias, fp32-accurate via hi*hi+hi*lo+lo*hi.
// Block: 128(M) x 128(N), K-tile 64, 256 thr = 8 warps (4x2), warp tile 32x64.
// Smem stride 72 halves: conflict-free + 16B-aligned for ldmatrix.
#define SSTR 72
#define KT   64

#define LDSM4(r, addr) \
    asm volatile("ldmatrix.sync.aligned.m8n8.x4.shared.b16 {%0,%1,%2,%3}, [%4];" \
        : "=r"((r)[0]), "=r"((r)[1]), "=r"((r)[2]), "=r"((r)[3]) : "r"(addr))

#define MMA16816(c, a, b0, b1) \
    asm volatile("mma.sync.aligned.m16n8k16.row.col.f32.bf16.bf16.f32 " \
        "{%0,%1,%2,%3},{%4,%5,%6,%7},{%8,%9},{%0,%1,%2,%3};" \
        : "+f"((c)[0]), "+f"((c)[1]), "+f"((c)[2]), "+f"((c)[3]) \
        : "r"((a)[0]), "r"((a)[1]), "r"((a)[2]), "r"((a)[3]), "r"(b0), "r"(b1))

__global__ void __launch_bounds__(256, 2) gemm_mma(
    const float* __restrict__ A, const float* __restrict__ bias) {
    extern __shared__ char dynsmem[];
    __nv_bfloat16* sAH = (__nv_bfloat16*)dynsmem;        // [128][72]
    __nv_bfloat16* sAL = sAH + 128 * SSTR;
    __nv_bfloat16* sWH = sAH + 2 * 128 * SSTR;           // [n][k] [128][72]
    __nv_bfloat16* sWL = sAH + 3 * 128 * SSTR;

    const int tid = threadIdx.x;
    const int lane = tid & 31;
    const int wid = tid >> 5;
    const int wr = wid >> 1;     // 0..3 (m)
    const int wc = wid & 1;      // 0..1 (n)
    const int bm = blockIdx.x * 128;

    const unsigned sb = (unsigned)__cvta_generic_to_shared(dynsmem);
    const unsigned AHb = sb;
    const unsigned ALb = sb + 128 * SSTR * 2;
    const unsigned WHb = sb + 2 * 128 * SSTR * 2;
    const unsigned WLb = sb + 3 * 128 * SSTR * 2;

    // ldmatrix per-lane offsets (bytes)
    const int aRow = ((lane >> 3) & 1) * 8 + (lane & 7);
    const int aColH = (lane >> 4) * 8;
    const unsigned aOff0 = (unsigned)(((wr * 32 + 0  + aRow) * SSTR + aColH) * 2);
    const unsigned aOff1 = (unsigned)(((wr * 32 + 16 + aRow) * SSTR + aColH) * 2);
    const int bRow = (lane >> 4) * 8 + (lane & 7);
    const int bColH = ((lane >> 3) & 1) * 8;
    const unsigned bOff = (unsigned)(((wc * 64 + bRow) * SSTR + bColH) * 2);

    // gmem load coords
    const int lm = tid >> 1;                 // row within tile (0..127)
    const int lk = (tid & 1) * 32;           // k offset base
    int arow = bm + lm;
    if (arow >= N_NODES) arow = N_NODES - 1;
    const float* Ap = A + (size_t)arow * TD + lk;
    const __nv_bfloat16* WHp = g_WtH + lm * TD + lk;
    const __nv_bfloat16* WLp = g_WtL + lm * TD + lk;

    float c[2][8][4];
#pragma unroll
    for (int i = 0; i < 2; i++)
#pragma unroll
        for (int j = 0; j < 8; j++)
#pragma unroll
            for (int q = 0; q < 4; q++) c[i][j][q] = 0.f;

    for (int t = 0; t < TD / KT; t++) {
        const int k0 = t * KT;
        // A tile: load fp32, split hi/lo
#pragma unroll
        for (int cc = 0; cc < 8; cc++) {
            float4 v = *(const float4*)(Ap + k0 + cc * 4);
            __nv_bfloat16 h0 = __float2bfloat16(v.x);
            __nv_bfloat16 h1 = __float2bfloat16(v.y);
            __nv_bfloat16 h2 = __float2bfloat16(v.z);
            __nv_bfloat16 h3 = __float2bfloat16(v.w);
            __nv_bfloat162 hA, hB, lA, lB;
            hA.x = h0; hA.y = h1; hB.x = h2; hB.y = h3;
            lA.x = __float2bfloat16(v.x - __bfloat162float(h0));
            lA.y = __float2bfloat16(v.y - __bfloat162float(h1));
            lB.x = __float2bfloat16(v.z - __bfloat162float(h2));
            lB.y = __float2bfloat16(v.w - __bfloat162float(h3));
            int so = lm * SSTR + lk + cc * 4;
            *(__nv_bfloat162*)(sAH + so)     = hA;
            *(__nv_bfloat162*)(sAH + so + 2) = hB;
            *(__nv_bfloat162*)(sAL + so)     = lA;
            *(__nv_bfloat162*)(sAL + so + 2) = lB;
        }
        // W tile: already bf16/transposed; bulk copy
#pragma unroll
        for (int cc = 0; cc < 4; cc++) {
            uint4 vh = *(const uint4*)(WHp + k0 + cc * 8);
            uint4 vl = *(const uint4*)(WLp + k0 + cc * 8);
            int so = lm * SSTR + lk + cc * 8;
            *(uint4*)(sWH + so) = vh;
            *(uint4*)(sWL + so) = vl;
        }
        __syncthreads();

#pragma unroll
        for (int kk = 0; kk < KT / 16; kk++) {
            const unsigned ko = kk * 32;  // 16 halves
            unsigned aH[2][4], aL[2][4];
            LDSM4(aH[0], AHb + aOff0 + ko);
            LDSM4(aH[1], AHb + aOff1 + ko);
            LDSM4(aL[0], ALb + aOff0 + ko);
            LDSM4(aL[1], ALb + aOff1 + ko);
#pragma unroll
            for (int jj = 0; jj < 4; jj++) {
                unsigned bH[4], bL[4];
                const unsigned bo = bOff + jj * (16 * SSTR * 2) + ko;
                LDSM4(bH, WHb + bo);
                LDSM4(bL, WLb + bo);
#pragma unroll
                for (int i = 0; i < 2; i++) {
                    MMA16816(c[i][2 * jj],     aH[i], bH[0], bH[1]);
                    MMA16816(c[i][2 * jj],     aH[i], bL[0], bL[1]);
                    MMA16816(c[i][2 * jj],     aL[i], bH[0], bH[1]);
                    MMA16816(c[i][2 * jj + 1], aH[i], bH[2], bH[3]);
                    MMA16816(c[i][2 * jj + 1], aH[i], bL[2], bL[3]);
                    MMA16816(c[i][2 * jj + 1], aL[i], bH[2], bH[3]);
                }
            }
        }
        __syncthreads();
    }

    // epilogue: + bias, -> fp16
#pragma unroll
    for (int i = 0; i < 2; i++) {
        int r0 = bm + wr * 32 + i * 16 + (lane >> 2);
        int r1 = r0 + 8;
#pragma unroll
        for (int j = 0; j < 8; j++) {
            int n = wc * 64 + j * 8 + (lane & 3) * 2;
            float2 bb = *(const float2*)(bias + n);
            __half2 v0 = __floats2half2_rn(c[i][j][0] + bb.x, c[i][j][1] + bb.y);
            __half2 v1 = __floats2half2_rn(c[i][j][2] + bb.x, c[i][j][3] + bb.y);
            if (r0 < N_NODES) *(__half2*)(g_h16A + (size_t)r0 * HID + n) = v0;
            if (r1 < N_NODES) *(__half2*)(g_h16A + (size_t)r1 * HID + n) = v1;
        }
    }
}

// ---------------- column mean + hypernetwork scale ----------------
__global__ void col_partial(int sel) {
    const __half* __restrict__ h = sel ? g_h16B : g_h16A;
    float s = 0.f;
    int cidx = threadIdx.x;
    for (int r = blockIdx.x; r < N_NODES; r += gridDim.x)
        s += __half2float(h[(size_t)r * HID + cidx]);
    g_part[blockIdx.x * HID + cidx] = s;
}

__global__ void mk_scale(const float* __restrict__ W1, const float* __restrict__ b1,
                         const float* __restrict__ W2, const float* __restrict__ b2) {
    __shared__ float g[HID];
    __shared__ float t1[HID];
    int j = threadIdx.x;
    float s = 0.f;
    for (int b = 0; b < NPART; b++) s += g_part[b * HID + j];
    g[j] = s * (1.0f / (float)N_NODES);
    __syncthreads();
    float a = b1[j];
    for (int k = 0; k < HID; k++) a += g[k] * W1[k * HID + j];
    t1[j] = fmaxf(a, 0.f);
    __syncthreads();
    float o = b2[j];
    for (int k = 0; k < HID; k++) o += t1[k] * W2[k * HID + j];
    g_scale[j] = o;
}

// ---------------- aggregation (fp16 rows, warp-per-segment, MLP=4) ----------------
__global__ void edge_agg(int sel) {
    const __half* __restrict__ h = sel ? g_h16B : g_h16A;
    int w = (blockIdx.x * blockDim.x + threadIdx.x) >> 5;
    int lane = threadIdx.x & 31;
    if (w >= N_EDGES) return;
    int beg = g_eoff[w], end = g_eoff[w + 1];
    float4 acc = make_float4(0.f, 0.f, 0.f, 0.f);
    for (int c = beg; c < end; c += 32) {
        int m = end - c;
        if (m > 32) m = 32;
        int myid = (lane < m) ? g_enodes[c + lane] : 0;
        int t = 0;
        for (; t + 4 <= m; t += 4) {
            int n0 = __shfl_sync(0xffffffffu, myid, t + 0);
            int n1 = __shfl_sync(0xffffffffu, myid, t + 1);
            int n2 = __shfl_sync(0xffffffffu, myid, t + 2);
            int n3 = __shfl_sync(0xffffffffu, myid, t + 3);
            float4 v0 = load4h(h + (size_t)n0 * HID, lane);
            float4 v1 = load4h(h + (size_t)n1 * HID, lane);
            float4 v2 = load4h(h + (size_t)n2 * HID, lane);
            float4 v3 = load4h(h + (size_t)n3 * HID, lane);
            acc.x += v0.x + v1.x + v2.x + v3.x;
            acc.y += v0.y + v1.y + v2.y + v3.y;
            acc.z += v0.z + v1.z + v2.z + v3.z;
            acc.w += v0.w + v1.w + v2.w + v3.w;
        }
        for (; t < m; t++) {
            int nid = __shfl_sync(0xffffffffu, myid, t);
            float4 v = load4h(h + (size_t)nid * HID, lane);
            acc.x += v.x; acc.y += v.y; acc.z += v.z; acc.w += v.w;
        }
    }
    float inv = 1.0f / fmaxf((float)(end - beg), 1.0f);
    store4h(g_ef16 + (size_t)w * HID, lane,
            make_float4(acc.x * inv, acc.y * inv, acc.z * inv, acc.w * inv));
}

// to_out: 0 = write g_h16B (fp16), 1 = write d_out (fp32)
__global__ void node_agg(float4* __restrict__ out_arg, int to_out) {
    int w = (blockIdx.x * blockDim.x + threadIdx.x) >> 5;
    int lane = threadIdx.x & 31;
    if (w >= N_NODES) return;
    int beg = g_noff[w], end = g_noff[w + 1];
    float4 acc = make_float4(0.f, 0.f, 0.f, 0.f);
    for (int c = beg; c < end; c += 32) {
        int m = end - c;
        if (m > 32) m = 32;
        int myid = (lane < m) ? g_nedges[c + lane] : 0;
        int t = 0;
        for (; t + 4 <= m; t += 4) {
            int e0 = __shfl_sync(0xffffffffu, myid, t + 0);
            int e1 = __shfl_sync(0xffffffffu, myid, t + 1);
            int e2 = __shfl_sync(0xffffffffu, myid, t + 2);
            int e3 = __shfl_sync(0xffffffffu, myid, t + 3);
            float4 v0 = load4h(g_ef16 + (size_t)e0 * HID, lane);
            float4 v1 = load4h(g_ef16 + (size_t)e1 * HID, lane);
            float4 v2 = load4h(g_ef16 + (size_t)e2 * HID, lane);
            float4 v3 = load4h(g_ef16 + (size_t)e3 * HID, lane);
            acc.x += v0.x + v1.x + v2.x + v3.x;
            acc.y += v0.y + v1.y + v2.y + v3.y;
            acc.z += v0.z + v1.z + v2.z + v3.z;
            acc.w += v0.w + v1.w + v2.w + v3.w;
        }
        for (; t < m; t++) {
            int eid = __shfl_sync(0xffffffffu, myid, t);
            float4 v = load4h(g_ef16 + (size_t)eid * HID, lane);
            acc.x += v.x; acc.y += v.y; acc.z += v.z; acc.w += v.w;
        }
    }
    float inv = 1.0f / fmaxf((float)(end - beg), 1.0f);
    float4 sc = ((const float4*)g_scale)[lane];
    float4 o;
    o.x = fmaxf(acc.x * inv * sc.x, 0.f);
    o.y = fmaxf(acc.y * inv * sc.y, 0.f);
    o.z = fmaxf(acc.z * inv * sc.z, 0.f);
    o.w = fmaxf(acc.w * inv * sc.w, 0.f);
    if (to_out) out_arg[(size_t)w * 32 + lane] = o;
    else        store4h(g_h16B + (size_t)w * HID, lane, o);
}

// ---------------- launch ----------------
extern "C" void kernel_launch(void* const* d_in, const int* in_sizes, int n_in,
                              void* d_out, int out_size) {
    const float* text = (const float*)d_in[0];
    const float* Wp   = (const float*)d_in[1];
    const float* bp   = (const float*)d_in[2];
    const float* W1a  = (const float*)d_in[3];
    const float* b1a  = (const float*)d_in[4];
    const float* W2a  = (const float*)d_in[5];
    const float* b2a  = (const float*)d_in[6];
    const float* W1b  = (const float*)d_in[7];
    const float* b1b  = (const float*)d_in[8];
    const float* W2b  = (const float*)d_in[9];
    const float* b2b  = (const float*)d_in[10];
    const int* node_idx = (const int*)d_in[11];
    const int* edge_idx = (const int*)d_in[12];

    const int NBE = (N_EDGES + 255) / 256;
    const int NBN = (N_NODES + 255) / 256;
    const int NBI = (N_INC + 255) / 256;
    const int SMEM_GEMM = 4 * 128 * SSTR * 2;  // 73728 B

    static cudaStream_t s2 = nullptr;
    static cudaEvent_t ev0, evCSR, evG, evS1, evN0, evS2;
    if (!s2) {
        cudaStreamCreateWithFlags(&s2, cudaStreamNonBlocking);
        cudaEventCreateWithFlags(&ev0,   cudaEventDisableTiming);
        cudaEventCreateWithFlags(&evCSR, cudaEventDisableTiming);
        cudaEventCreateWithFlags(&evG,   cudaEventDisableTiming);
        cudaEventCreateWithFlags(&evS1,  cudaEventDisableTiming);
        cudaEventCreateWithFlags(&evN0,  cudaEventDisableTiming);
        cudaEventCreateWithFlags(&evS2,  cudaEventDisableTiming);
        cudaFuncSetAttribute(gemm_mma,
            cudaFuncAttributeMaxDynamicSharedMemorySize, SMEM_GEMM);
    }

    // fork: CSR build on s2, GEMM on main stream
    cudaEventRecord(ev0, 0);
    cudaStreamWaitEvent(s2, ev0, 0);

    zero_counts<<<NBN, 256, 0, s2>>>();
    hist_kernel<<<NBI, 256, 0, s2>>>(node_idx, edge_idx);
    seg_block_sums<<<NBE, 256, 0, s2>>>(0);
    scan_bsums<<<1, 512, 0, s2>>>(NBE);
    scan_final<<<NBE, 256, 0, s2>>>(0);
    seg_block_sums<<<NBN, 256, 0, s2>>>(1);
    scan_bsums<<<1, 512, 0, s2>>>(NBN);
    scan_final<<<NBN, 256, 0, s2>>>(1);
    csr_fill<<<NBI, 256, 0, s2>>>(node_idx, edge_idx);
    cudaEventRecord(evCSR, s2);

    w_prep<<<(TD * HID + 255) / 256, 256>>>(Wp);
    gemm_mma<<<(N_NODES + 127) / 128, 256, SMEM_GEMM>>>(text, bp);
    cudaEventRecord(evG, 0);

    // layer 1: stats on s2 overlap edge_agg on main
    cudaStreamWaitEvent(s2, evG, 0);
    col_partial<<<NPART, 128, 0, s2>>>(0);
    mk_scale<<<1, 128, 0, s2>>>(W1a, b1a, W2a, b2a);
    cudaEventRecord(evS1, s2);

    cudaStreamWaitEvent((cudaStream_t)0, evCSR, 0);
    edge_agg<<<N_EDGES / 8, 256>>>(0);
    cudaStreamWaitEvent((cudaStream_t)0, evS1, 0);
    node_agg<<<N_NODES / 8, 256>>>((float4*)d_out, 0);
    cudaEventRecord(evN0, 0);

    // layer 2
    cudaStreamWaitEvent(s2, evN0, 0);
    col_partial<<<NPART, 128, 0, s2>>>(1);
    mk_scale<<<1, 128, 0, s2>>>(W1b, b1b, W2b, b2b);
    cudaEventRecord(evS2, s2);

    edge_agg<<<N_EDGES / 8, 256>>>(1);
    cudaStreamWaitEvent((cudaStream_t)0, evS2, 0);
    node_agg<<<N_NODES / 8, 256>>>((float4*)d_out, 1);
}

// round 4
// speedup vs baseline: 1.6180x; 1.0107x over previous
#include <cuda_runtime.h>
#include <cuda_fp16.h>
#include <cuda_bf16.h>

#define N_NODES 100000
#define N_EDGES 20000
#define N_INC   800000
#define TD      384
#define HID     128
#define NPART   1024
#define NBE     79      // ceil(20000/256)
#define NBN     391     // ceil(100000/256)
#define NBI     3125    // ceil(800000/256)

// ---------------- device scratch ----------------
__device__ __align__(16) __half g_h16A[N_NODES * HID];
__device__ __align__(16) __half g_h16B[N_NODES * HID];
__device__ __align__(16) __half g_ef16[N_EDGES * HID];
__device__ __nv_bfloat16 g_WtH[HID * TD];
__device__ __nv_bfloat16 g_WtL[HID * TD];
__device__ int   g_ecnt[N_EDGES];
__device__ int   g_ncnt[N_NODES];
__device__ int   g_ecur[N_EDGES];
__device__ int   g_ncur[N_NODES];
__device__ int   g_eoff[N_EDGES + 1];
__device__ int   g_noff[N_NODES + 1];
__device__ int   g_enodes[N_INC];
__device__ int   g_nedges[N_INC];
__device__ int   g_bsumE[128];
__device__ int   g_bsumN[512];
__device__ float g_part[NPART * HID];
__device__ __align__(16) float g_scale[HID];

// ---------------- CSR construction ----------------
__global__ void zero_counts() {
    int i = blockIdx.x * blockDim.x + threadIdx.x;
    if (i < N_EDGES) { g_ecnt[i] = 0; g_ecur[i] = 0; }
    if (i < N_NODES) { g_ncnt[i] = 0; g_ncur[i] = 0; }
}

__global__ void hist_kernel(const int* __restrict__ ni, const int* __restrict__ ei) {
    int i = blockIdx.x * blockDim.x + threadIdx.x;
    if (i < N_INC) {
        atomicAdd(&g_ecnt[ei[i]], 1);
        atomicAdd(&g_ncnt[ni[i]], 1);
    }
}

// combined block sums for edges (blocks [0,NBE)) and nodes (blocks [NBE,NBE+NBN))
__global__ void segB() {
    int b = blockIdx.x;
    const int* __restrict__ cnt;
    int n;
    int* bs;
    if (b < NBE) { cnt = g_ecnt; n = N_EDGES; bs = g_bsumE; }
    else { b -= NBE; cnt = g_ncnt; n = N_NODES; bs = g_bsumN; }
    __shared__ int s[256];
    int t = threadIdx.x;
    int i = b * 256 + t;
    s[t] = (i < n) ? cnt[i] : 0;
    __syncthreads();
    for (int o = 128; o > 0; o >>= 1) {
        if (t < o) s[t] += s[t + o];
        __syncthreads();
    }
    if (t == 0) bs[b] = s[0];
}

// block 0 scans edge bsums, block 1 scans node bsums
__global__ void scanB() {
    int* bs = blockIdx.x ? g_bsumN : g_bsumE;
    int nb = blockIdx.x ? NBN : NBE;
    __shared__ int s[512];
    int t = threadIdx.x;
    int v = (t < nb) ? bs[t] : 0;
    s[t] = v;
    __syncthreads();
    for (int o = 1; o < 512; o <<= 1) {
        int x = (t >= o) ? s[t - o] : 0;
        __syncthreads();
        s[t] += x;
        __syncthreads();
    }
    if (t < nb) bs[t] = s[t] - v;  // exclusive
}

__global__ void scanfB() {
    int b = blockIdx.x;
    const int* __restrict__ cnt;
    const int* bs;
    int* off;
    int n;
    if (b < NBE) { cnt = g_ecnt; bs = g_bsumE; off = g_eoff; n = N_EDGES; }
    else { b -= NBE; cnt = g_ncnt; bs = g_bsumN; off = g_noff; n = N_NODES; }
    __shared__ int s[256];
    int t = threadIdx.x;
    int i = b * 256 + t;
    int v = (i < n) ? cnt[i] : 0;
    s[t] = v;
    __syncthreads();
    for (int o = 1; o < 256; o <<= 1) {
        int x = (t >= o) ? s[t - o] : 0;
        __syncthreads();
        s[t] += x;
        __syncthreads();
    }
    if (i < n) off[i] = bs[b] + s[t] - v;
    if (i == 0) off[n] = N_INC;
}

__global__ void csr_fill(const int* __restrict__ ni, const int* __restrict__ ei) {
    int i = blockIdx.x * blockDim.x + threadIdx.x;
    if (i >= N_INC) return;
    int e = ei[i], n = ni[i];
    int pe = g_eoff[e] + atomicAdd(&g_ecur[e], 1);
    g_enodes[pe] = n;
    int pn = g_noff[n] + atomicAdd(&g_ncur[n], 1);
    g_nedges[pn] = e;
}

// ---------------- W prep: fp32 [k][n] -> bf16 hi/lo transposed [n][k] ----------------
__global__ void w_prep(const float* __restrict__ W) {
    int i = blockIdx.x * blockDim.x + threadIdx.x;
    if (i >= TD * HID) return;
    int n = i & (HID - 1);
    int k = i >> 7;
    float x = W[k * HID + n];
    __nv_bfloat16 hi = __float2bfloat16(x);
    float lo = x - __bfloat162float(hi);
    g_WtH[n * TD + k] = hi;
    g_WtL[n * TD + k] = __float2bfloat16(lo);
}

// ---------------- tensor-core projection GEMM (bf16-split, mma.sync) ----------------
#define SSTR 72
#define KT   64

#define LDSM4(r, addr) \
    asm volatile("ldmatrix.sync.aligned.m8n8.x4.shared.b16 {%0,%1,%2,%3}, [%4];" \
        : "=r"((r)[0]), "=r"((r)[1]), "=r"((r)[2]), "=r"((r)[3]) : "r"(addr))

#define MMA16816(c, a, b0, b1) \
    asm volatile("mma.sync.aligned.m16n8k16.row.col.f32.bf16.bf16.f32 " \
        "{%0,%1,%2,%3},{%4,%5,%6,%7},{%8,%9},{%0,%1,%2,%3};" \
        : "+f"((c)[0]), "+f"((c)[1]), "+f"((c)[2]), "+f"((c)[3]) \
        : "r"((a)[0]), "r"((a)[1]), "r"((a)[2]), "r"((a)[3]), "r"(b0), "r"(b1))

__global__ void __launch_bounds__(256, 2) gemm_mma(
    const float* __restrict__ A, const float* __restrict__ bias) {
    extern __shared__ char dynsmem[];
    __nv_bfloat16* sAH = (__nv_bfloat16*)dynsmem;
    __nv_bfloat16* sAL = sAH + 128 * SSTR;
    __nv_bfloat16* sWH = sAH + 2 * 128 * SSTR;
    __nv_bfloat16* sWL = sAH + 3 * 128 * SSTR;

    const int tid = threadIdx.x;
    const int lane = tid & 31;
    const int wid = tid >> 5;
    const int wr = wid >> 1;
    const int wc = wid & 1;
    const int bm = blockIdx.x * 128;

    const unsigned sb = (unsigned)__cvta_generic_to_shared(dynsmem);
    const unsigned AHb = sb;
    const unsigned ALb = sb + 128 * SSTR * 2;
    const unsigned WHb = sb + 2 * 128 * SSTR * 2;
    const unsigned WLb = sb + 3 * 128 * SSTR * 2;

    const int aRow = ((lane >> 3) & 1) * 8 + (lane & 7);
    const int aColH = (lane >> 4) * 8;
    const unsigned aOff0 = (unsigned)(((wr * 32 + 0  + aRow) * SSTR + aColH) * 2);
    const unsigned aOff1 = (unsigned)(((wr * 32 + 16 + aRow) * SSTR + aColH) * 2);
    const int bRow = (lane >> 4) * 8 + (lane & 7);
    const int bColH = ((lane >> 3) & 1) * 8;
    const unsigned bOff = (unsigned)(((wc * 64 + bRow) * SSTR + bColH) * 2);

    const int lm = tid >> 1;
    const int lk = (tid & 1) * 32;
    int arow = bm + lm;
    if (arow >= N_NODES) arow = N_NODES - 1;
    const float* Ap = A + (size_t)arow * TD + lk;
    const __nv_bfloat16* WHp = g_WtH + lm * TD + lk;
    const __nv_bfloat16* WLp = g_WtL + lm * TD + lk;

    float c[2][8][4];
#pragma unroll
    for (int i = 0; i < 2; i++)
#pragma unroll
        for (int j = 0; j < 8; j++)
#pragma unroll
            for (int q = 0; q < 4; q++) c[i][j][q] = 0.f;

    for (int t = 0; t < TD / KT; t++) {
        const int k0 = t * KT;
#pragma unroll
        for (int cc = 0; cc < 8; cc++) {
            float4 v = *(const float4*)(Ap + k0 + cc * 4);
            __nv_bfloat16 h0 = __float2bfloat16(v.x);
            __nv_bfloat16 h1 = __float2bfloat16(v.y);
            __nv_bfloat16 h2 = __float2bfloat16(v.z);
            __nv_bfloat16 h3 = __float2bfloat16(v.w);
            __nv_bfloat162 hA, hB, lA, lB;
            hA.x = h0; hA.y = h1; hB.x = h2; hB.y = h3;
            lA.x = __float2bfloat16(v.x - __bfloat162float(h0));
            lA.y = __float2bfloat16(v.y - __bfloat162float(h1));
            lB.x = __float2bfloat16(v.z - __bfloat162float(h2));
            lB.y = __float2bfloat16(v.w - __bfloat162float(h3));
            int so = lm * SSTR + lk + cc * 4;
            *(__nv_bfloat162*)(sAH + so)     = hA;
            *(__nv_bfloat162*)(sAH + so + 2) = hB;
            *(__nv_bfloat162*)(sAL + so)     = lA;
            *(__nv_bfloat162*)(sAL + so + 2) = lB;
        }
#pragma unroll
        for (int cc = 0; cc < 4; cc++) {
            uint4 vh = *(const uint4*)(WHp + k0 + cc * 8);
            uint4 vl = *(const uint4*)(WLp + k0 + cc * 8);
            int so = lm * SSTR + lk + cc * 8;
            *(uint4*)(sWH + so) = vh;
            *(uint4*)(sWL + so) = vl;
        }
        __syncthreads();

#pragma unroll
        for (int kk = 0; kk < KT / 16; kk++) {
            const unsigned ko = kk * 32;
            unsigned aH[2][4], aL[2][4];
            LDSM4(aH[0], AHb + aOff0 + ko);
            LDSM4(aH[1], AHb + aOff1 + ko);
            LDSM4(aL[0], ALb + aOff0 + ko);
            LDSM4(aL[1], ALb + aOff1 + ko);
#pragma unroll
            for (int jj = 0; jj < 4; jj++) {
                unsigned bH[4], bL[4];
                const unsigned bo = bOff + jj * (16 * SSTR * 2) + ko;
                LDSM4(bH, WHb + bo);
                LDSM4(bL, WLb + bo);
#pragma unroll
                for (int i = 0; i < 2; i++) {
                    MMA16816(c[i][2 * jj],     aH[i], bH[0], bH[1]);
                    MMA16816(c[i][2 * jj],     aH[i], bL[0], bL[1]);
                    MMA16816(c[i][2 * jj],     aL[i], bH[0], bH[1]);
                    MMA16816(c[i][2 * jj + 1], aH[i], bH[2], bH[3]);
                    MMA16816(c[i][2 * jj + 1], aH[i], bL[2], bL[3]);
                    MMA16816(c[i][2 * jj + 1], aL[i], bH[2], bH[3]);
                }
            }
        }
        __syncthreads();
    }

#pragma unroll
    for (int i = 0; i < 2; i++) {
        int r0 = bm + wr * 32 + i * 16 + (lane >> 2);
        int r1 = r0 + 8;
#pragma unroll
        for (int j = 0; j < 8; j++) {
            int n = wc * 64 + j * 8 + (lane & 3) * 2;
            float2 bb = *(const float2*)(bias + n);
            __half2 v0 = __floats2half2_rn(c[i][j][0] + bb.x, c[i][j][1] + bb.y);
            __half2 v1 = __floats2half2_rn(c[i][j][2] + bb.x, c[i][j][3] + bb.y);
            if (r0 < N_NODES) *(__half2*)(g_h16A + (size_t)r0 * HID + n) = v0;
            if (r1 < N_NODES) *(__half2*)(g_h16A + (size_t)r1 * HID + n) = v1;
        }
    }
}

// ---------------- column mean + hypernetwork scale ----------------
__global__ void col_partial(int sel) {
    const __half* __restrict__ h = sel ? g_h16B : g_h16A;
    float s = 0.f;
    int cidx = threadIdx.x;
    for (int r = blockIdx.x; r < N_NODES; r += gridDim.x)
        s += __half2float(h[(size_t)r * HID + cidx]);
    g_part[blockIdx.x * HID + cidx] = s;
}

__global__ void mk_scale(const float* __restrict__ W1, const float* __restrict__ b1,
                         const float* __restrict__ W2, const float* __restrict__ b2) {
    __shared__ float g[HID];
    __shared__ float t1[HID];
    int j = threadIdx.x;
    float s = 0.f;
    for (int b = 0; b < NPART; b++) s += g_part[b * HID + j];
    g[j] = s * (1.0f / (float)N_NODES);
    __syncthreads();
    float a = b1[j];
    for (int k = 0; k < HID; k++) a += g[k] * W1[k * HID + j];
    t1[j] = fmaxf(a, 0.f);
    __syncthreads();
    float o = b2[j];
    for (int k = 0; k < HID; k++) o += t1[k] * W2[k * HID + j];
    g_scale[j] = o;
}

// ---------------- aggregation: 2 rows/warp-load via uint4 (16B/lane) ----------------
__device__ __forceinline__ void acc8(float* a, uint4 v) {
    __half2 h0 = *reinterpret_cast<__half2*>(&v.x);
    __half2 h1 = *reinterpret_cast<__half2*>(&v.y);
    __half2 h2 = *reinterpret_cast<__half2*>(&v.z);
    __half2 h3 = *reinterpret_cast<__half2*>(&v.w);
    float2 f0 = __half22float2(h0), f1 = __half22float2(h1);
    float2 f2 = __half22float2(h2), f3 = __half22float2(h3);
    a[0] += f0.x; a[1] += f0.y; a[2] += f1.x; a[3] += f1.y;
    a[4] += f2.x; a[5] += f2.y; a[6] += f3.x; a[7] += f3.y;
}

// warp-per-segment sum over gathered fp16 rows; returns acc[8] in lanes 0-15
// (lane L holds columns 8L..8L+7). idxbuf = CSR ids; h = row source.
__device__ __forceinline__ void seg_sum(const int* __restrict__ ids, int beg, int m,
                                        const __half* __restrict__ h,
                                        int lane, float* acc) {
    const int half = lane >> 4;
    const int cpos = lane & 15;
    for (int c = 0; c < m; c += 32) {
        int rem = m - c;
        if (rem > 32) rem = 32;
        int myid = (lane < rem) ? ids[beg + c + lane] : 0;
        int t = 0;
        for (; t + 8 <= rem; t += 8) {
#pragma unroll
            for (int p = 0; p < 4; p++) {
                int id = __shfl_sync(0xffffffffu, myid, t + 2 * p + half);
                uint4 v = *(const uint4*)(h + (size_t)id * HID + cpos * 8);
                acc8(acc, v);
            }
        }
        for (; t < rem; t += 2) {
            int idx = t + half;
            bool valid = idx < rem;
            int id = __shfl_sync(0xffffffffu, myid, valid ? idx : t);
            uint4 v = *(const uint4*)(h + (size_t)id * HID + cpos * 8);
            if (valid) acc8(acc, v);
        }
    }
#pragma unroll
    for (int i = 0; i < 8; i++)
        acc[i] += __shfl_xor_sync(0xffffffffu, acc[i], 16);
}

__global__ void edge_agg(int sel) {
    const __half* __restrict__ h = sel ? g_h16B : g_h16A;
    int w = (blockIdx.x * blockDim.x + threadIdx.x) >> 5;
    int lane = threadIdx.x & 31;
    if (w >= N_EDGES) return;
    int beg = g_eoff[w], end = g_eoff[w + 1];
    int m = end - beg;
    float acc[8] = {0.f, 0.f, 0.f, 0.f, 0.f, 0.f, 0.f, 0.f};
    seg_sum(g_enodes, beg, m, h, lane, acc);
    if (lane < 16) {
        float inv = 1.0f / fmaxf((float)m, 1.0f);
        __half2 p0 = __floats2half2_rn(acc[0] * inv, acc[1] * inv);
        __half2 p1 = __floats2half2_rn(acc[2] * inv, acc[3] * inv);
        __half2 p2 = __floats2half2_rn(acc[4] * inv, acc[5] * inv);
        __half2 p3 = __floats2half2_rn(acc[6] * inv, acc[7] * inv);
        uint4 u;
        u.x = *reinterpret_cast<unsigned*>(&p0);
        u.y = *reinterpret_cast<unsigned*>(&p1);
        u.z = *reinterpret_cast<unsigned*>(&p2);
        u.w = *reinterpret_cast<unsigned*>(&p3);
        ((uint4*)(g_ef16 + (size_t)w * HID))[lane] = u;
    }
}

// to_out: 0 = write g_h16B (fp16), 1 = write d_out (fp32)
__global__ void node_agg(float* __restrict__ out_arg, int to_out) {
    int w = (blockIdx.x * blockDim.x + threadIdx.x) >> 5;
    int lane = threadIdx.x & 31;
    if (w >= N_NODES) return;
    int beg = g_noff[w], end = g_noff[w + 1];
    int m = end - beg;
    float acc[8] = {0.f, 0.f, 0.f, 0.f, 0.f, 0.f, 0.f, 0.f};
    seg_sum(g_nedges, beg, m, g_ef16, lane, acc);
    if (lane < 16) {
        float inv = 1.0f / fmaxf((float)m, 1.0f);
        float4 s0 = ((const float4*)g_scale)[lane * 2];
        float4 s1 = ((const float4*)g_scale)[lane * 2 + 1];
        float r0 = fmaxf(acc[0] * inv * s0.x, 0.f);
        float r1 = fmaxf(acc[1] * inv * s0.y, 0.f);
        float r2 = fmaxf(acc[2] * inv * s0.z, 0.f);
        float r3 = fmaxf(acc[3] * inv * s0.w, 0.f);
        float r4 = fmaxf(acc[4] * inv * s1.x, 0.f);
        float r5 = fmaxf(acc[5] * inv * s1.y, 0.f);
        float r6 = fmaxf(acc[6] * inv * s1.z, 0.f);
        float r7 = fmaxf(acc[7] * inv * s1.w, 0.f);
        if (to_out) {
            float* orow = out_arg + (size_t)w * HID + lane * 8;
            *(float4*)orow = make_float4(r0, r1, r2, r3);
            *(float4*)(orow + 4) = make_float4(r4, r5, r6, r7);
        } else {
            __half2 p0 = __floats2half2_rn(r0, r1);
            __half2 p1 = __floats2half2_rn(r2, r3);
            __half2 p2 = __floats2half2_rn(r4, r5);
            __half2 p3 = __floats2half2_rn(r6, r7);
            uint4 u;
            u.x = *reinterpret_cast<unsigned*>(&p0);
            u.y = *reinterpret_cast<unsigned*>(&p1);
            u.z = *reinterpret_cast<unsigned*>(&p2);
            u.w = *reinterpret_cast<unsigned*>(&p3);
            ((uint4*)(g_h16B + (size_t)w * HID))[lane] = u;
        }
    }
}

// ---------------- launch ----------------
extern "C" void kernel_launch(void* const* d_in, const int* in_sizes, int n_in,
                              void* d_out, int out_size) {
    const float* text = (const float*)d_in[0];
    const float* Wp   = (const float*)d_in[1];
    const float* bp   = (const float*)d_in[2];
    const float* W1a  = (const float*)d_in[3];
    const float* b1a  = (const float*)d_in[4];
    const float* W2a  = (const float*)d_in[5];
    const float* b2a  = (const float*)d_in[6];
    const float* W1b  = (const float*)d_in[7];
    const float* b1b  = (const float*)d_in[8];
    const float* W2b  = (const float*)d_in[9];
    const float* b2b  = (const float*)d_in[10];
    const int* node_idx = (const int*)d_in[11];
    const int* edge_idx = (const int*)d_in[12];

    const int SMEM_GEMM = 4 * 128 * SSTR * 2;  // 73728 B

    static cudaStream_t s2 = nullptr;
    static cudaEvent_t ev0, evCSR, evG, evS1, evN0, evS2;
    if (!s2) {
        cudaStreamCreateWithFlags(&s2, cudaStreamNonBlocking);
        cudaEventCreateWithFlags(&ev0,   cudaEventDisableTiming);
        cudaEventCreateWithFlags(&evCSR, cudaEventDisableTiming);
        cudaEventCreateWithFlags(&evG,   cudaEventDisableTiming);
        cudaEventCreateWithFlags(&evS1,  cudaEventDisableTiming);
        cudaEventCreateWithFlags(&evN0,  cudaEventDisableTiming);
        cudaEventCreateWithFlags(&evS2,  cudaEventDisableTiming);
        cudaFuncSetAttribute(gemm_mma,
            cudaFuncAttributeMaxDynamicSharedMemorySize, SMEM_GEMM);
    }

    // fork s2 from capture stream
    cudaEventRecord(ev0, 0);
    cudaStreamWaitEvent(s2, ev0, 0);

    // submission #0 (main): w_prep
    w_prep<<<(TD * HID + 255) / 256, 256>>>(Wp);
    // submissions #1-#5 (s2): CSR scans
    zero_counts<<<NBN, 256, 0, s2>>>();
    hist_kernel<<<NBI, 256, 0, s2>>>(node_idx, edge_idx);
    segB<<<NBE + NBN, 256, 0, s2>>>();
    scanB<<<2, 512, 0, s2>>>();
    scanfB<<<NBE + NBN, 256, 0, s2>>>();
    // submission #6 (main): GEMM  <-- ncu profiles this one
    gemm_mma<<<(N_NODES + 127) / 128, 256, SMEM_GEMM>>>(text, bp);
    cudaEventRecord(evG, 0);
    // submission #7 (s2): csr_fill (runs concurrent with gemm)
    csr_fill<<<NBI, 256, 0, s2>>>(node_idx, edge_idx);
    cudaEventRecord(evCSR, s2);

    // layer-1 stats on s2, overlapped with edge_agg on main
    cudaStreamWaitEvent(s2, evG, 0);
    col_partial<<<NPART, 128, 0, s2>>>(0);
    mk_scale<<<1, 128, 0, s2>>>(W1a, b1a, W2a, b2a);
    cudaEventRecord(evS1, s2);

    cudaStreamWaitEvent((cudaStream_t)0, evCSR, 0);
    edge_agg<<<N_EDGES / 8, 256>>>(0);
    cudaStreamWaitEvent((cudaStream_t)0, evS1, 0);
    node_agg<<<N_NODES / 8, 256>>>((float*)d_out, 0);
    cudaEventRecord(evN0, 0);

    // layer 2
    cudaStreamWaitEvent(s2, evN0, 0);
    col_partial<<<NPART, 128, 0, s2>>>(1);
    mk_scale<<<1, 128, 0, s2>>>(W1b, b1b, W2b, b2b);
    cudaEventRecord(evS2, s2);

    edge_agg<<<N_EDGES / 8, 256>>>(1);
    cudaStreamWaitEvent((cudaStream_t)0, evS2, 0);
    node_agg<<<N_NODES / 8, 256>>>((float*)d_out, 1);
}